// round 1
// baseline (speedup 1.0000x reference)
#include <cuda_runtime.h>

#define NY 64
#define NU 32
#define NH 512
#define NHRZ 2048
#define BB 128
#define LCH 32
#define PCH 64
#define KIN 544   // NH + NU

// ---------------- device scratch (static, no allocation) ----------------
__device__ float d_A[NH * NH];              // A (transposed recurrence weight), x' = x @ A
__device__ float d_Pow[5][NH * NH];         // A^2, A^4, A^8, A^16, A^32
__device__ float d_Cbuf[NH * LCH * NY];     // [512][2048], col block j = C_j = A^j Wy^T
__device__ float d_Gp[LCH * NU * NH];       // [1024][512], row block d = G'_d = Bm A^d
__device__ float d_Hd[(LCH - 1) * NU * NY]; // [31][32][64], Hd_d = Bm A^d Wy^T
__device__ float d_yb[LCH * NY];            // per-in-chunk-position output bias
__device__ float d_bL[NH];                  // s_L = c * sum_{i<L} A^i
__device__ float d_Xc[(PCH + 1) * BB * NH]; // chunk-start states
__device__ float d_S[PCH * BB * NH];        // per-chunk aggregated inputs (+ bL)

// ---------------- prep: transpose A, Bm, C0, x0 ----------------
__global__ void prep_kernel(const float* __restrict__ y0,
                            const float* __restrict__ y2x_w,
                            const float* __restrict__ y2x_b,
                            const float* __restrict__ xu2x_w,
                            const float* __restrict__ x2y_w) {
    int idx = blockIdx.x * blockDim.x + threadIdx.x;
    int stride = gridDim.x * blockDim.x;
    // A[p][q] = xu2x_w[q][p]
    for (int t = idx; t < NH * NH; t += stride) {
        int p = t / NH, q = t % NH;
        d_A[p * NH + q] = xu2x_w[q * KIN + p];
    }
    // Gp block 0 = Bm: Bm[u][h] = xu2x_w[h][NH+u]
    for (int t = idx; t < NU * NH; t += stride) {
        int u = t / NH, h = t % NH;
        d_Gp[u * NH + h] = xu2x_w[h * KIN + NH + u];
    }
    // C_0 = Wy^T: Cbuf[h][n] = x2y_w[n][h]
    for (int t = idx; t < NH * NY; t += stride) {
        int h = t / NY, n = t % NY;
        d_Cbuf[h * (LCH * NY) + n] = x2y_w[n * NH + h];
    }
    // x0 = y0 @ y2x_w^T + y2x_b  -> Xc[0]
    for (int t = idx; t < BB * NH; t += stride) {
        int b = t / NH, h = t % NH;
        float acc = y2x_b[h];
        #pragma unroll 8
        for (int n = 0; n < NY; n++) acc += y0[b * NY + n] * y2x_w[h * NY + n];
        d_Xc[b * NH + h] = acc;
    }
}

// ---------------- svec: bias chains s_j, yb_j, bL ----------------
__global__ void svec_kernel(const float* __restrict__ xu2x_w,
                            const float* __restrict__ xu2x_b,
                            const float* __restrict__ x2y_w,
                            const float* __restrict__ x2y_b) {
    __shared__ float s[NH];
    int t = threadIdx.x;
    s[t] = 0.0f;
    __syncthreads();
    for (int j = 0; j < LCH; j++) {
        if (t < NY) {
            float acc = x2y_b[t];
            for (int h = 0; h < NH; h++) acc += s[h] * x2y_w[t * NH + h];
            d_yb[j * NY + t] = acc;
        }
        float acc = xu2x_b[t];
        for (int p = 0; p < NH; p++) acc += s[p] * xu2x_w[t * KIN + p];
        __syncthreads();
        s[t] = acc;
        __syncthreads();
    }
    d_bL[t] = s[t];
}

// ---------------- generic small GEMM: C = A @ B (row-major, strided) ----------------
// 32x32 tile, 256 threads, 2x2 per thread. M, N, K multiples of 32.
__global__ void gemm_small(const float* __restrict__ A, const float* __restrict__ B,
                           float* __restrict__ C, int K, int lda, int ldb, int ldc) {
    __shared__ float As[32][33];
    __shared__ float Bs[32][33];
    int tid = threadIdx.x;
    int tx = tid & 15, ty = tid >> 4;
    int row0 = blockIdx.y * 32, col0 = blockIdx.x * 32;
    float a00 = 0.f, a01 = 0.f, a10 = 0.f, a11 = 0.f;
    for (int k0 = 0; k0 < K; k0 += 32) {
        #pragma unroll
        for (int r = 0; r < 4; r++) {
            int e = tid + 256 * r;
            int ar = e >> 5, ac = e & 31;
            As[ar][ac] = A[(row0 + ar) * lda + k0 + ac];
            Bs[ar][ac] = B[(k0 + ar) * ldb + col0 + ac];
        }
        __syncthreads();
        #pragma unroll
        for (int k = 0; k < 32; k++) {
            float x0 = As[ty * 2 + 0][k], x1 = As[ty * 2 + 1][k];
            float w0 = Bs[k][tx * 2 + 0], w1 = Bs[k][tx * 2 + 1];
            a00 += x0 * w0; a01 += x0 * w1;
            a10 += x1 * w0; a11 += x1 * w1;
        }
        __syncthreads();
    }
    int r = row0 + ty * 2, c = col0 + tx * 2;
    C[r * ldc + c] = a00;       C[r * ldc + c + 1] = a01;
    C[(r + 1) * ldc + c] = a10; C[(r + 1) * ldc + c + 1] = a11;
}

// ---------------- S = Umat @ Grev + bL : M=8192, K=1024, N=512 ----------------
// 64x64 tile, 256 threads, 4x4 per thread.
__global__ void s_kernel(const float* __restrict__ U) {
    __shared__ float As[16][68];
    __shared__ float Bs[16][64];
    int tid = threadIdx.x;
    int tx = tid & 15, ty = tid >> 4;
    int row0 = blockIdx.y * 64;
    int col0 = blockIdx.x * 64;
    float acc[16];
    #pragma unroll
    for (int i = 0; i < 16; i++) acc[i] = 0.f;

    int m  = tid >> 2;
    int kq = (tid & 3) * 4;
    int q = row0 + m;
    int p = q >> 7, b = q & 127;
    long aBase = (long)p * (LCH * BB * NU) + (long)b * NU; // U[(p*32+i)*128 + b][u]
    int n4 = (tid & 15) * 4, kb = tid >> 4;

    for (int k0 = 0; k0 < LCH * NU; k0 += 16) {
        int kk = k0 + kq;
        int i = kk >> 5, u = kk & 31;
        float4 av = *(const float4*)(U + aBase + (long)i * (BB * NU) + u);
        As[kq + 0][m] = av.x; As[kq + 1][m] = av.y;
        As[kq + 2][m] = av.z; As[kq + 3][m] = av.w;
        int kkb = k0 + kb;
        int ib = kkb >> 5, ub = kkb & 31;
        const float* brow = d_Gp + ((31 - ib) * 32 + ub) * NH + col0;
        *(float4*)&Bs[kb][n4] = *(const float4*)(brow + n4);
        __syncthreads();
        #pragma unroll
        for (int k = 0; k < 16; k++) {
            float4 a  = *(float4*)&As[k][ty * 4];
            float4 bv = *(float4*)&Bs[k][tx * 4];
            acc[0]  += a.x * bv.x; acc[1]  += a.x * bv.y; acc[2]  += a.x * bv.z; acc[3]  += a.x * bv.w;
            acc[4]  += a.y * bv.x; acc[5]  += a.y * bv.y; acc[6]  += a.y * bv.z; acc[7]  += a.y * bv.w;
            acc[8]  += a.z * bv.x; acc[9]  += a.z * bv.y; acc[10] += a.z * bv.z; acc[11] += a.z * bv.w;
            acc[12] += a.w * bv.x; acc[13] += a.w * bv.y; acc[14] += a.w * bv.z; acc[15] += a.w * bv.w;
        }
        __syncthreads();
    }
    #pragma unroll
    for (int ii = 0; ii < 4; ii++) {
        int r = row0 + ty * 4 + ii;
        #pragma unroll
        for (int jj = 0; jj < 4; jj++) {
            int c = col0 + tx * 4 + jj;
            d_S[(long)r * NH + c] = acc[ii * 4 + jj] + d_bL[c];
        }
    }
}

// ---------------- sequential: Xc[p+1] = Xc[p] @ A^32 + S[p] ----------------
__global__ void seq_kernel(int p) {
    __shared__ float As[32][33];
    __shared__ float Bs[32][33];
    int tid = threadIdx.x;
    int tx = tid & 15, ty = tid >> 4;
    int row0 = blockIdx.y * 32, col0 = blockIdx.x * 32;
    const float* Xp = d_Xc + (long)p * (BB * NH);
    const float* W  = d_Pow[4];
    float a00 = 0.f, a01 = 0.f, a10 = 0.f, a11 = 0.f;
    for (int k0 = 0; k0 < NH; k0 += 32) {
        #pragma unroll
        for (int r = 0; r < 4; r++) {
            int e = tid + 256 * r;
            int ar = e >> 5, ac = e & 31;
            As[ar][ac] = Xp[(row0 + ar) * NH + k0 + ac];
            Bs[ar][ac] = W[(k0 + ar) * NH + col0 + ac];
        }
        __syncthreads();
        #pragma unroll
        for (int k = 0; k < 32; k++) {
            float x0 = As[ty * 2 + 0][k], x1 = As[ty * 2 + 1][k];
            float w0 = Bs[k][tx * 2 + 0], w1 = Bs[k][tx * 2 + 1];
            a00 += x0 * w0; a01 += x0 * w1;
            a10 += x1 * w0; a11 += x1 * w1;
        }
        __syncthreads();
    }
    float* Xn = d_Xc + (long)(p + 1) * (BB * NH);
    const float* Sp = d_S + (long)p * (BB * NH);
    int r = row0 + ty * 2, c = col0 + tx * 2;
    Xn[r * NH + c]           = a00 + Sp[r * NH + c];
    Xn[r * NH + c + 1]       = a01 + Sp[r * NH + c + 1];
    Xn[(r + 1) * NH + c]     = a10 + Sp[(r + 1) * NH + c];
    Xn[(r + 1) * NH + c + 1] = a11 + Sp[(r + 1) * NH + c + 1];
}

// ---------------- output pass ----------------
// One tile = (p, j, half): Y[p*32+j][half*64 .. +63][0..63]
// K_eff = 512 + 32*j : k<512 from Xc[p] x C_j, k>=512 from U x Hd (causal blocks only)
__global__ void out_kernel(const float* __restrict__ U, float* __restrict__ out) {
    __shared__ float As[16][68];
    __shared__ float Bs[16][64];
    int t = blockIdx.x;
    int pj = t >> 1, half = t & 1;
    int p = pj >> 5, j = pj & 31;
    int tid = threadIdx.x;
    int tx = tid & 15, ty = tid >> 4;
    int KT = 32 + 2 * j; // K-tiles of 16

    int row0 = half * 64;
    int m  = tid >> 2;
    int kq = (tid & 3) * 4;
    int b = row0 + m;
    const float* xcRow = d_Xc + (long)p * (BB * NH) + (long)b * NH;
    long uBase = (long)p * (LCH * BB * NU) + (long)b * NU;
    int n4 = (tid & 15) * 4, kb = tid >> 4;

    float acc[16];
    #pragma unroll
    for (int i = 0; i < 16; i++) acc[i] = 0.f;

    for (int kt = 0; kt < KT; kt++) {
        int k0 = kt * 16;
        float4 av;
        if (k0 < NH) {
            av = *(const float4*)(xcRow + k0 + kq);
        } else {
            int kc = k0 + kq - NH;
            int i = kc >> 5, u = kc & 31;
            av = *(const float4*)(U + uBase + (long)i * (BB * NU) + u);
        }
        As[kq + 0][m] = av.x; As[kq + 1][m] = av.y;
        As[kq + 2][m] = av.z; As[kq + 3][m] = av.w;

        int kk = k0 + kb;
        const float* brow;
        if (kk < NH) {
            brow = d_Cbuf + (long)kk * (LCH * NY) + j * NY;
        } else {
            int kc = kk - NH;
            int i = kc >> 5, u = kc & 31;
            brow = d_Hd + ((j - 1 - i) * NU + u) * NY;
        }
        *(float4*)&Bs[kb][n4] = *(const float4*)(brow + n4);
        __syncthreads();
        #pragma unroll
        for (int k = 0; k < 16; k++) {
            float4 a  = *(float4*)&As[k][ty * 4];
            float4 bv = *(float4*)&Bs[k][tx * 4];
            acc[0]  += a.x * bv.x; acc[1]  += a.x * bv.y; acc[2]  += a.x * bv.z; acc[3]  += a.x * bv.w;
            acc[4]  += a.y * bv.x; acc[5]  += a.y * bv.y; acc[6]  += a.y * bv.z; acc[7]  += a.y * bv.w;
            acc[8]  += a.z * bv.x; acc[9]  += a.z * bv.y; acc[10] += a.z * bv.z; acc[11] += a.z * bv.w;
            acc[12] += a.w * bv.x; acc[13] += a.w * bv.y; acc[14] += a.w * bv.z; acc[15] += a.w * bv.w;
        }
        __syncthreads();
    }
    float* orow = out + (long)pj * (BB * NY);
    #pragma unroll
    for (int ii = 0; ii < 4; ii++) {
        int r = row0 + ty * 4 + ii;
        #pragma unroll
        for (int jj = 0; jj < 4; jj++) {
            int c = tx * 4 + jj;
            orow[r * NY + c] = acc[ii * 4 + jj] + d_yb[j * NY + c];
        }
    }
}

// ---------------- host ----------------
extern "C" void kernel_launch(void* const* d_in, const int* in_sizes, int n_in,
                              void* d_out, int out_size) {
    const float* y0     = (const float*)d_in[0];
    const float* U      = (const float*)d_in[1];
    const float* y2x_w  = (const float*)d_in[2];
    const float* y2x_b  = (const float*)d_in[3];
    const float* xu2x_w = (const float*)d_in[4];
    const float* xu2x_b = (const float*)d_in[5];
    const float* x2y_w  = (const float*)d_in[6];
    const float* x2y_b  = (const float*)d_in[7];
    float* out = (float*)d_out;

    float *pA, *pP, *pCbuf, *pGp, *pHd;
    cudaGetSymbolAddress((void**)&pA, d_A);
    cudaGetSymbolAddress((void**)&pP, d_Pow);
    cudaGetSymbolAddress((void**)&pCbuf, d_Cbuf);
    cudaGetSymbolAddress((void**)&pGp, d_Gp);
    cudaGetSymbolAddress((void**)&pHd, d_Hd);
    const int SZ = NH * NH;

    prep_kernel<<<128, 256>>>(y0, y2x_w, y2x_b, xu2x_w, x2y_w);
    svec_kernel<<<1, NH>>>(xu2x_w, xu2x_b, x2y_w, x2y_b);

    // A^2, A^4, A^8, A^16, A^32 by squaring
    gemm_small<<<dim3(16, 16), 256>>>(pA, pA, pP + 0 * SZ, NH, NH, NH, NH);
    gemm_small<<<dim3(16, 16), 256>>>(pP + 0 * SZ, pP + 0 * SZ, pP + 1 * SZ, NH, NH, NH, NH);
    gemm_small<<<dim3(16, 16), 256>>>(pP + 1 * SZ, pP + 1 * SZ, pP + 2 * SZ, NH, NH, NH, NH);
    gemm_small<<<dim3(16, 16), 256>>>(pP + 2 * SZ, pP + 2 * SZ, pP + 3 * SZ, NH, NH, NH, NH);
    gemm_small<<<dim3(16, 16), 256>>>(pP + 3 * SZ, pP + 3 * SZ, pP + 4 * SZ, NH, NH, NH, NH);

    // C_j doubling: C[j+2^k] = A^{2^k} @ C[j]
    for (int k = 0; k < 5; k++) {
        const float* mult = (k == 0) ? pA : (pP + (k - 1) * SZ);
        int w = NY << k; // 64 * 2^k columns already present
        gemm_small<<<dim3(w / 32, 16), 256>>>(mult, pCbuf, pCbuf + w, NH, NH, LCH * NY, LCH * NY);
    }
    // G'_d doubling: G'[d+2^k] = G'[d] @ A^{2^k}
    for (int k = 0; k < 5; k++) {
        const float* mult = (k == 0) ? pA : (pP + (k - 1) * SZ);
        int rows = NU << k;
        gemm_small<<<dim3(16, rows / 32), 256>>>(pGp, mult, pGp + rows * NH, NH, NH, NH, NH);
    }
    // Hd_d = G'_d @ C_0  (stacked: M = 31*32 = 992)
    gemm_small<<<dim3(2, 31), 256>>>(pGp, pCbuf, pHd, NH, NH, LCH * NY, NY);

    // S = Umat @ Grev + bL
    s_kernel<<<dim3(NH / 64, (PCH * BB) / 64), 256>>>(U);

    // 64 sequential chunk steps
    for (int p = 0; p < PCH; p++)
        seq_kernel<<<dim3(NH / 32, BB / 32), 256>>>(p);

    // output pass: 2049 (p,j) tiles x 2 row-halves
    out_kernel<<<2 * (PCH * LCH + 1), 256>>>(U, out);

    (void)in_sizes; (void)n_in; (void)out_size;
}